// round 3
// baseline (speedup 1.0000x reference)
#include <cuda_runtime.h>
#include <math.h>

// Problem constants
#define NB   16384      // batch
#define DIN  2048       // S*C
#define HID  512
#define LAT  64
#define NCODE 9         // 3x3 SOM grid

// ---------------------------------------------------------------------------
// Scratch (device globals; no allocation allowed in kernel_launch)
// ---------------------------------------------------------------------------
__device__ float g_H1[(size_t)NB * HID];     // 33.5 MB
__device__ float g_H2[(size_t)NB * HID];     // 33.5 MB
__device__ float g_Z [(size_t)NB * LAT];     // 4.2 MB
__device__ int   g_K [NB];
__device__ float g_h1q[NCODE * HID];
__device__ float g_h2q[NCODE * HID];
__device__ float g_xq [NCODE * DIN];         // dec_q outputs for the 9 codes
__device__ float g_mse_e_part[2048];
__device__ float g_mse_q_part[2048];
__device__ float g_commit_part[64];
__device__ float g_som_part[64];

// ---------------------------------------------------------------------------
// Generic tiled SGEMM: C = act(A[MxK] @ W[KxN] + bias[N])
// BM=128, BN=128, BK=8, 256 threads, 8x8 per-thread tile.
// Requirements: M % 128 == 0, K % 8 == 0, N % 4 == 0 (bounds-checked on N).
// ACT: 0=none, 1=relu, 2=tanh
// ---------------------------------------------------------------------------
template <int ACT>
__global__ __launch_bounds__(256) void gemm_bias_act(
    const float* __restrict__ A, const float* __restrict__ W,
    const float* __restrict__ bias, float* __restrict__ C,
    int M, int N, int K)
{
    __shared__ float As[8][128];
    __shared__ float Bs[8][128];

    const int tid = threadIdx.x;
    const int bx = blockIdx.x, by = blockIdx.y;
    const int tRow = tid >> 4;    // 0..15
    const int tCol = tid & 15;    // 0..15

    const int aRow = tid >> 1;          // 0..127
    const int aCol = (tid & 1) * 4;     // 0 or 4
    const int bRow = tid >> 5;          // 0..7
    const int bCol = (tid & 31) * 4;    // 0..124

    const float* Aptr = A + (size_t)(by * 128 + aRow) * K + aCol;
    const int gcolB = bx * 128 + bCol;
    const bool bInb = (gcolB < N);      // N%4==0 so whole float4 in/out

    float acc[8][8];
#pragma unroll
    for (int i = 0; i < 8; i++)
#pragma unroll
        for (int j = 0; j < 8; j++) acc[i][j] = 0.f;

    for (int k0 = 0; k0 < K; k0 += 8) {
        float4 av = *(const float4*)(Aptr + k0);
        As[aCol + 0][aRow] = av.x;
        As[aCol + 1][aRow] = av.y;
        As[aCol + 2][aRow] = av.z;
        As[aCol + 3][aRow] = av.w;

        float4 bv = make_float4(0.f, 0.f, 0.f, 0.f);
        if (bInb) bv = *(const float4*)(W + (size_t)(k0 + bRow) * N + gcolB);
        *(float4*)&Bs[bRow][bCol] = bv;
        __syncthreads();

#pragma unroll
        for (int kk = 0; kk < 8; kk++) {
            float ra[8], rb[8];
#pragma unroll
            for (int i = 0; i < 8; i++) ra[i] = As[kk][tRow * 8 + i];
#pragma unroll
            for (int j = 0; j < 8; j++) rb[j] = Bs[kk][tCol * 8 + j];
#pragma unroll
            for (int i = 0; i < 8; i++)
#pragma unroll
                for (int j = 0; j < 8; j++)
                    acc[i][j] = fmaf(ra[i], rb[j], acc[i][j]);
        }
        __syncthreads();
    }

#pragma unroll
    for (int i = 0; i < 8; i++) {
        const int r = by * 128 + tRow * 8 + i;
#pragma unroll
        for (int j = 0; j < 8; j++) {
            const int c = bx * 128 + tCol * 8 + j;
            if (c < N) {
                float v = acc[i][j] + bias[c];
                if (ACT == 1) v = fmaxf(v, 0.f);
                else if (ACT == 2) v = tanhf(v);
                C[(size_t)r * N + c] = v;
            }
        }
    }
}

// ---------------------------------------------------------------------------
// Per-row argmin over the 9 codebook vectors + commit/som loss partials.
// commit contribution = dist[k]; som = dist[k] + 4 neighbor terms where an
// out-of-grid neighbor contributes ||z||^2 (neighbor vector masked to 0).
// ---------------------------------------------------------------------------
__global__ __launch_bounds__(256) void argmin_som_kernel(
    const float* __restrict__ Z, const float* __restrict__ emb,
    int* __restrict__ Kout,
    float* __restrict__ commit_part, float* __restrict__ som_part)
{
    __shared__ float se[NCODE * LAT];
    const int tid = threadIdx.x;
    for (int i = tid; i < NCODE * LAT; i += blockDim.x) se[i] = emb[i];
    __syncthreads();

    const int b = blockIdx.x * blockDim.x + tid;
    float commit = 0.f, som = 0.f;
    if (b < NB) {
        const float* z = Z + (size_t)b * LAT;
        float zr[LAT];
        float zn = 0.f;
#pragma unroll
        for (int d = 0; d < LAT; d++) { zr[d] = z[d]; zn = fmaf(zr[d], zr[d], zn); }

        float dist[NCODE];
        int k = 0;
        float best = 3.4e38f;
#pragma unroll
        for (int c = 0; c < NCODE; c++) {
            float s = 0.f;
#pragma unroll
            for (int d = 0; d < LAT; d++) {
                float df = zr[d] - se[c * LAT + d];
                s = fmaf(df, df, s);
            }
            dist[c] = s;
            if (s < best) { best = s; k = c; }   // first-min tie break, matches argmin
        }
        Kout[b] = k;
        const int k1 = k / 3, k2 = k % 3;
        commit = dist[k];
        som = dist[k];
        som += (k1 < 2) ? dist[(k1 + 1) * 3 + k2] : zn;   // up
        som += (k1 > 0) ? dist[(k1 - 1) * 3 + k2] : zn;   // down
        som += (k2 < 2) ? dist[k1 * 3 + k2 + 1]   : zn;   // right
        som += (k2 > 0) ? dist[k1 * 3 + k2 - 1]   : zn;   // left
    }

    __shared__ float r1[256], r2[256];
    r1[tid] = commit; r2[tid] = som;
    __syncthreads();
    for (int s = 128; s > 0; s >>= 1) {
        if (tid < s) { r1[tid] += r1[tid + s]; r2[tid] += r2[tid + s]; }
        __syncthreads();
    }
    if (tid == 0) { commit_part[blockIdx.x] = r1[0]; som_part[blockIdx.x] = r2[0]; }
}

// ---------------------------------------------------------------------------
// dec_q evaluated on the 9 codebook vectors only (z_q has only 9 values!)
// ---------------------------------------------------------------------------
__global__ void dq_layer1(const float* __restrict__ emb, const float* __restrict__ w,
                          const float* __restrict__ bias, float* __restrict__ out)
{
    const int c = blockIdx.x, j = threadIdx.x;   // 9 blocks x 512 threads
    float s = bias[j];
    for (int d = 0; d < LAT; d++) s = fmaf(emb[c * LAT + d], w[d * HID + j], s);
    out[c * HID + j] = fmaxf(s, 0.f);
}

__global__ void dq_layer2(const float* __restrict__ h, const float* __restrict__ w,
                          const float* __restrict__ bias, float* __restrict__ out)
{
    const int c = blockIdx.x, j = threadIdx.x;   // 9 blocks x 512 threads
    float s = bias[j];
    for (int i = 0; i < HID; i++) s = fmaf(h[c * HID + i], w[i * HID + j], s);
    out[c * HID + j] = fmaxf(s, 0.f);
}

__global__ void dq_layer3(const float* __restrict__ h, const float* __restrict__ w,
                          const float* __restrict__ bias, float* __restrict__ out)
{
    const int c = blockIdx.y;                                  // 9
    const int n = blockIdx.x * blockDim.x + threadIdx.x;       // 2048
    float s = bias[n];
    for (int i = 0; i < HID; i++) s = fmaf(h[c * HID + i], w[(size_t)i * DIN + n], s);
    out[c * DIN + n] = s;
}

// ---------------------------------------------------------------------------
// Final fused GEMM: x_e = G2 @ de_w3 + b3;  Out = x_e + XQ[k[row]];
// accumulates per-block partials of sum((x-x_e)^2) and sum((x-x_q)^2).
// K=512, N=2048, M=16384 fixed.
// ---------------------------------------------------------------------------
__global__ __launch_bounds__(256) void final_gemm_kernel(
    const float* __restrict__ A, const float* __restrict__ W,
    const float* __restrict__ bias,
    const float* __restrict__ X, const float* __restrict__ XQ,
    const int* __restrict__ Kidx,
    float* __restrict__ Out,
    float* __restrict__ mse_e_part, float* __restrict__ mse_q_part)
{
    const int K = HID, N = DIN;
    __shared__ float As[8][128];
    __shared__ float Bs[8][128];

    const int tid = threadIdx.x;
    const int bx = blockIdx.x, by = blockIdx.y;
    const int tRow = tid >> 4;
    const int tCol = tid & 15;

    const int aRow = tid >> 1;
    const int aCol = (tid & 1) * 4;
    const int bRow = tid >> 5;
    const int bCol = (tid & 31) * 4;

    const float* Aptr = A + (size_t)(by * 128 + aRow) * K + aCol;
    const int gcolB = bx * 128 + bCol;

    float acc[8][8];
#pragma unroll
    for (int i = 0; i < 8; i++)
#pragma unroll
        for (int j = 0; j < 8; j++) acc[i][j] = 0.f;

    for (int k0 = 0; k0 < K; k0 += 8) {
        float4 av = *(const float4*)(Aptr + k0);
        As[aCol + 0][aRow] = av.x;
        As[aCol + 1][aRow] = av.y;
        As[aCol + 2][aRow] = av.z;
        As[aCol + 3][aRow] = av.w;
        float4 bv = *(const float4*)(W + (size_t)(k0 + bRow) * N + gcolB);
        *(float4*)&Bs[bRow][bCol] = bv;
        __syncthreads();

#pragma unroll
        for (int kk = 0; kk < 8; kk++) {
            float ra[8], rb[8];
#pragma unroll
            for (int i = 0; i < 8; i++) ra[i] = As[kk][tRow * 8 + i];
#pragma unroll
            for (int j = 0; j < 8; j++) rb[j] = Bs[kk][tCol * 8 + j];
#pragma unroll
            for (int i = 0; i < 8; i++)
#pragma unroll
                for (int j = 0; j < 8; j++)
                    acc[i][j] = fmaf(ra[i], rb[j], acc[i][j]);
        }
        __syncthreads();
    }

    float se = 0.f, sq = 0.f;
    int kidx[8];
#pragma unroll
    for (int i = 0; i < 8; i++) kidx[i] = Kidx[by * 128 + tRow * 8 + i];

#pragma unroll
    for (int i = 0; i < 8; i++) {
        const int r = by * 128 + tRow * 8 + i;
#pragma unroll
        for (int j = 0; j < 8; j++) {
            const int c = bx * 128 + tCol * 8 + j;
            const float xe  = acc[i][j] + bias[c];
            const float xqv = XQ[kidx[i] * DIN + c];
            const float xv  = X[(size_t)r * DIN + c];
            Out[(size_t)r * DIN + c] = xe + xqv;
            const float d1 = xv - xe;  se = fmaf(d1, d1, se);
            const float d2 = xv - xqv; sq = fmaf(d2, d2, sq);
        }
    }

    __shared__ float r1[256], r2[256];
    r1[tid] = se; r2[tid] = sq;
    __syncthreads();
    for (int s = 128; s > 0; s >>= 1) {
        if (tid < s) { r1[tid] += r1[tid + s]; r2[tid] += r2[tid + s]; }
        __syncthreads();
    }
    if (tid == 0) {
        const int bid = by * gridDim.x + bx;   // gridDim = (16, 128) -> 2048 blocks
        mse_e_part[bid] = r1[0];
        mse_q_part[bid] = r2[0];
    }
}

// ---------------------------------------------------------------------------
// Deterministic finalize: double-precision sum of partials -> loss scalar.
// ---------------------------------------------------------------------------
__global__ void finalize_kernel(
    const float* __restrict__ mse_e, const float* __restrict__ mse_q,
    const float* __restrict__ commit, const float* __restrict__ som,
    float* __restrict__ out_loss, int has_loss)
{
    __shared__ double sh[256];
    const int tid = threadIdx.x;

    double a = 0.0;
    for (int i = tid; i < 2048; i += 256) a += (double)mse_e[i] + (double)mse_q[i];
    sh[tid] = a; __syncthreads();
    for (int s = 128; s > 0; s >>= 1) { if (tid < s) sh[tid] += sh[tid + s]; __syncthreads(); }
    const double mse_sum = sh[0]; __syncthreads();

    double c = 0.0;
    for (int i = tid; i < 64; i += 256) c += (double)commit[i];
    sh[tid] = c; __syncthreads();
    for (int s = 128; s > 0; s >>= 1) { if (tid < s) sh[tid] += sh[tid + s]; __syncthreads(); }
    const double commit_sum = sh[0]; __syncthreads();

    double so = 0.0;
    for (int i = tid; i < 64; i += 256) so += (double)som[i];
    sh[tid] = so; __syncthreads();
    for (int s = 128; s > 0; s >>= 1) { if (tid < s) sh[tid] += sh[tid + s]; __syncthreads(); }
    const double som_sum = sh[0];

    if (tid == 0 && has_loss) {
        const double loss = mse_sum   / ((double)NB * DIN)       // both mse means share denom
                          + commit_sum / ((double)NB * LAT)
                          + som_sum    / ((double)NB * 5.0 * LAT);
        out_loss[0] = (float)loss;
    }
}

// ---------------------------------------------------------------------------
// Launch
// ---------------------------------------------------------------------------
extern "C" void kernel_launch(void* const* d_in, const int* in_sizes, int n_in,
                              void* d_out, int out_size)
{
    const float* x      = (const float*)d_in[0];
    // d_in[1] = y (unused by the forward computation)
    const float* enc_w1 = (const float*)d_in[2];
    const float* enc_b1 = (const float*)d_in[3];
    const float* enc_w2 = (const float*)d_in[4];
    const float* enc_b2 = (const float*)d_in[5];
    const float* enc_w3 = (const float*)d_in[6];
    const float* enc_b3 = (const float*)d_in[7];
    const float* dq_w1  = (const float*)d_in[8];
    const float* dq_b1  = (const float*)d_in[9];
    const float* dq_w2  = (const float*)d_in[10];
    const float* dq_b2  = (const float*)d_in[11];
    const float* dq_w3  = (const float*)d_in[12];
    const float* dq_b3  = (const float*)d_in[13];
    const float* de_w1  = (const float*)d_in[14];
    const float* de_b1  = (const float*)d_in[15];
    const float* de_w2  = (const float*)d_in[16];
    const float* de_b2  = (const float*)d_in[17];
    const float* de_w3  = (const float*)d_in[18];
    const float* de_b3  = (const float*)d_in[19];
    const float* emb    = (const float*)d_in[20];

    float* out = (float*)d_out;
    long long arr_off = (long long)out_size - (long long)NB * DIN;
    if (arr_off < 0) arr_off = 0;                  // defensive: loss slot optional
    float* outArr = out + arr_off;

    // Resolve all scratch addresses BEFORE any launch so graph capture sees a
    // pure launch sequence.
    float *H1, *H2, *Z, *h1q, *h2q, *xq, *msee, *mseq, *comm, *som;
    int* Kp;
    cudaGetSymbolAddress((void**)&H1,  g_H1);
    cudaGetSymbolAddress((void**)&H2,  g_H2);
    cudaGetSymbolAddress((void**)&Z,   g_Z);
    cudaGetSymbolAddress((void**)&Kp,  g_K);
    cudaGetSymbolAddress((void**)&h1q, g_h1q);
    cudaGetSymbolAddress((void**)&h2q, g_h2q);
    cudaGetSymbolAddress((void**)&xq,  g_xq);
    cudaGetSymbolAddress((void**)&msee, g_mse_e_part);
    cudaGetSymbolAddress((void**)&mseq, g_mse_q_part);
    cudaGetSymbolAddress((void**)&comm, g_commit_part);
    cudaGetSymbolAddress((void**)&som,  g_som_part);

    const dim3 blk(256);

    // Encoder
    gemm_bias_act<1><<<dim3(4, 128), blk>>>(x,  enc_w1, enc_b1, H1, NB, HID, DIN);
    gemm_bias_act<1><<<dim3(4, 128), blk>>>(H1, enc_w2, enc_b2, H2, NB, HID, HID);
    gemm_bias_act<2><<<dim3(1, 128), blk>>>(H2, enc_w3, enc_b3, Z,  NB, LAT, HID);

    // Argmin + commit/som partials
    argmin_som_kernel<<<64, 256>>>(Z, emb, Kp, comm, som);

    // dec_q on the 9 codebook vectors -> XQ table
    dq_layer1<<<NCODE, HID>>>(emb, dq_w1, dq_b1, h1q);
    dq_layer2<<<NCODE, HID>>>(h1q, dq_w2, dq_b2, h2q);
    dq_layer3<<<dim3(8, NCODE), 256>>>(h2q, dq_w3, dq_b3, xq);

    // dec_e (reuse H1/H2 buffers)
    gemm_bias_act<1><<<dim3(4, 128), blk>>>(Z,  de_w1, de_b1, H1, NB, HID, LAT);
    gemm_bias_act<1><<<dim3(4, 128), blk>>>(H1, de_w2, de_b2, H2, NB, HID, HID);

    // Final fused GEMM + output + MSE partials
    final_gemm_kernel<<<dim3(16, 128), blk>>>(H2, de_w3, de_b3, x, xq, Kp,
                                              outArr, msee, mseq);

    // Loss
    finalize_kernel<<<1, 256>>>(msee, mseq, comm, som, out, (int)(arr_off > 0));
}

// round 7
// speedup vs baseline: 1.6873x; 1.6873x over previous
#include <cuda_runtime.h>
#include <cuda_bf16.h>
#include <math.h>
#include <stdint.h>

// Problem constants
#define NB   16384
#define DIN  2048
#define HID  512
#define LAT  64
#define NCODE 9

// GEMM tiling
#define BM 128
#define BN 64
#define BKC 64
#define PK 72          // padded K stride (elements); 72*2=144B, 16B-aligned rows

// ---------------------------------------------------------------------------
// Scratch (16B-aligned: vectorized ld/st contract)
// ---------------------------------------------------------------------------
__device__ __align__(16) float g_H1[(size_t)NB * HID];
__device__ __align__(16) float g_H2[(size_t)NB * HID];
__device__ __align__(16) float g_Z [(size_t)NB * LAT];
__device__ __align__(16) int   g_K [NB];
__device__ __align__(16) float g_h1q[NCODE * HID];
__device__ __align__(16) float g_h2q[NCODE * HID];
__device__ __align__(16) float g_xq [NCODE * DIN];
__device__ __align__(16) float g_mse_e_part[4096];
__device__ __align__(16) float g_mse_q_part[4096];
__device__ __align__(16) float g_commit_part[64];
__device__ __align__(16) float g_som_part[64];

// Split+transposed weights: Wt[n][k] = W[k][n], hi/lo bf16
__device__ __align__(16) __nv_bfloat16 g_twh_e1[HID * DIN], g_twl_e1[HID * DIN];
__device__ __align__(16) __nv_bfloat16 g_twh_e2[HID * HID], g_twl_e2[HID * HID];
__device__ __align__(16) __nv_bfloat16 g_twh_e3[LAT * HID], g_twl_e3[LAT * HID];
__device__ __align__(16) __nv_bfloat16 g_twh_d1[HID * LAT], g_twl_d1[HID * LAT];
__device__ __align__(16) __nv_bfloat16 g_twh_d2[HID * HID], g_twl_d2[HID * HID];
__device__ __align__(16) __nv_bfloat16 g_twh_d3[DIN * HID], g_twl_d3[DIN * HID];

// ---------------------------------------------------------------------------
// mma / ldmatrix helpers (baseline PTX, sm_80+; compiles for compute_100)
// ---------------------------------------------------------------------------
__device__ __forceinline__ uint32_t smem_u32(const void* p) {
    uint32_t a;
    asm("{ .reg .u64 t; cvta.to.shared.u64 t, %1; cvt.u32.u64 %0, t; }" : "=r"(a) : "l"(p));
    return a;
}
__device__ __forceinline__ void ldmat_x4(uint32_t* r, uint32_t addr) {
    asm volatile("ldmatrix.sync.aligned.m8n8.x4.shared.b16 {%0,%1,%2,%3}, [%4];"
                 : "=r"(r[0]), "=r"(r[1]), "=r"(r[2]), "=r"(r[3]) : "r"(addr));
}
__device__ __forceinline__ void mma_bf16(float* c, const uint32_t* a, const uint32_t* b) {
    asm volatile(
        "mma.sync.aligned.m16n8k16.row.col.f32.bf16.bf16.f32 "
        "{%0,%1,%2,%3}, {%4,%5,%6,%7}, {%8,%9}, {%0,%1,%2,%3};"
        : "+f"(c[0]), "+f"(c[1]), "+f"(c[2]), "+f"(c[3])
        : "r"(a[0]), "r"(a[1]), "r"(a[2]), "r"(a[3]), "r"(b[0]), "r"(b[1]));
}

// ---------------------------------------------------------------------------
// Weight prep: Wt_hi/lo[n][k] = split(W[k][n])
// ---------------------------------------------------------------------------
__global__ __launch_bounds__(256) void transpose_split(
    const float* __restrict__ W, int K, int N,
    __nv_bfloat16* __restrict__ oh, __nv_bfloat16* __restrict__ ol)
{
    __shared__ float tile[32][33];
    const int n0 = blockIdx.x * 32, k0 = blockIdx.y * 32;
    const int tx = threadIdx.x & 31, ty = threadIdx.x >> 5;
    for (int i = ty; i < 32; i += 8) {
        int k = k0 + i, n = n0 + tx;
        tile[i][tx] = (k < K && n < N) ? W[(size_t)k * N + n] : 0.f;
    }
    __syncthreads();
    for (int i = ty; i < 32; i += 8) {
        int n = n0 + i, k = k0 + tx;
        if (n < N && k < K) {
            float a = tile[tx][i];
            __nv_bfloat16 hi = __float2bfloat16_rn(a);
            __nv_bfloat16 lo = __float2bfloat16_rn(a - __bfloat162float(hi));
            oh[(size_t)n * K + k] = hi;
            ol[(size_t)n * K + k] = lo;
        }
    }
}

// ---------------------------------------------------------------------------
// bf16 mma.sync GEMM: C[M x Ntot] = act(A[M x K] @ Wt^T + bias)
//   Wt [Ntot][K] bf16 hi/lo. 3-term split: AhBh + AhBl + AlBh (fp32 accum).
//   CTA: 128 x 64 tile. 8 warps (4 along M, 2 along N), warp tile 32x32.
// ---------------------------------------------------------------------------
template <int ACT, bool FUSED>
__global__ __launch_bounds__(256) void gemm_mma(
    const float* __restrict__ A,
    const __nv_bfloat16* __restrict__ Bh, const __nv_bfloat16* __restrict__ Bl,
    const float* __restrict__ bias, float* __restrict__ C,
    int K, int Ntot,
    const float* __restrict__ X, const float* __restrict__ XQ,
    const int* __restrict__ Kidx, float* __restrict__ Out,
    float* __restrict__ msee, float* __restrict__ mseq)
{
    extern __shared__ char smem[];
    __nv_bfloat16* sAh = (__nv_bfloat16*)smem;                 // BM*PK
    __nv_bfloat16* sAl = sAh + BM * PK;
    __nv_bfloat16* sBh = sAl + BM * PK;                        // BN*PK
    __nv_bfloat16* sBl = sBh + BN * PK;

    const int tid = threadIdx.x;
    const int lane = tid & 31;
    const int warp = tid >> 5;
    const int wm = warp & 3;            // 0..3  (M)
    const int wn = warp >> 2;           // 0..1  (N)
    const int bx = blockIdx.x, by = blockIdx.y;

    float acc[2][4][4];
#pragma unroll
    for (int mt = 0; mt < 2; mt++)
#pragma unroll
        for (int nt = 0; nt < 4; nt++)
#pragma unroll
            for (int e = 0; e < 4; e++) acc[mt][nt][e] = 0.f;

    const uint32_t uAh = smem_u32(sAh), uAl = smem_u32(sAl);
    const uint32_t uBh = smem_u32(sBh), uBl = smem_u32(sBl);

    const int arow = tid >> 1;              // 0..127
    const int acol = (tid & 1) * 32;        // 0 / 32
    const int brow = tid >> 2;              // 0..63
    const int bp0  = (tid & 3) * 2;         // uint4 index 0,2,4,6

    const int nChunks = K / BKC;

    for (int c = 0; c < nChunks; ++c) {
        const int kc = c * BKC;

        // ---- A chunk: 128x64 fp32 -> bf16 hi/lo (padded layout) ----
        {
            const float* ap = A + (size_t)(by * BM + arow) * K + kc + acol;
            uint32_t* dh = (uint32_t*)(sAh + arow * PK + acol);
            uint32_t* dl = (uint32_t*)(sAl + arow * PK + acol);
#pragma unroll
            for (int g = 0; g < 8; ++g) {
                float4 v = *(const float4*)(ap + g * 4);
                float f[4] = {v.x, v.y, v.z, v.w};
#pragma unroll
                for (int h = 0; h < 2; ++h) {
                    float a0 = f[h * 2], a1 = f[h * 2 + 1];
                    __nv_bfloat16 h0 = __float2bfloat16_rn(a0);
                    __nv_bfloat16 h1 = __float2bfloat16_rn(a1);
                    __nv_bfloat16 l0 = __float2bfloat16_rn(a0 - __bfloat162float(h0));
                    __nv_bfloat16 l1 = __float2bfloat16_rn(a1 - __bfloat162float(h1));
                    dh[g * 2 + h] = ((uint32_t)__bfloat16_as_ushort(h1) << 16) | __bfloat16_as_ushort(h0);
                    dl[g * 2 + h] = ((uint32_t)__bfloat16_as_ushort(l1) << 16) | __bfloat16_as_ushort(l0);
                }
            }
        }
        // ---- B chunk: 64 rows x 64 bf16, hi+lo (each row = 8 uint4) ----
        {
            const uint4* sh = (const uint4*)(Bh + (size_t)(bx * BN + brow) * K + kc);
            const uint4* sl = (const uint4*)(Bl + (size_t)(bx * BN + brow) * K + kc);
            uint4* dh = (uint4*)(sBh + brow * PK);
            uint4* dl = (uint4*)(sBl + brow * PK);
            dh[bp0] = sh[bp0];  dh[bp0 + 1] = sh[bp0 + 1];
            dl[bp0] = sl[bp0];  dl[bp0 + 1] = sl[bp0 + 1];
        }
        __syncthreads();

        // ---- MMA over 4 k-steps of 16 ----
#pragma unroll
        for (int ks = 0; ks < 4; ++ks) {
            const int kb = ks * 16;
            uint32_t ah[2][4], al[2][4];
#pragma unroll
            for (int mt = 0; mt < 2; mt++) {
                uint32_t off = (uint32_t)(((wm * 32 + mt * 16 + (lane & 15)) * PK
                                           + kb + (lane >> 4) * 8) * 2);
                ldmat_x4(ah[mt], uAh + off);
                ldmat_x4(al[mt], uAl + off);
            }
            uint32_t bh[4][2], bl[4][2];
#pragma unroll
            for (int ng = 0; ng < 2; ng++) {
                uint32_t off = (uint32_t)(((wn * 32 + ng * 16 + (lane & 15)) * PK
                                           + kb + (lane >> 4) * 8) * 2);
                uint32_t r[4];
                ldmat_x4(r, uBh + off);
                bh[ng * 2 + 0][0] = r[0]; bh[ng * 2 + 0][1] = r[2];
                bh[ng * 2 + 1][0] = r[1]; bh[ng * 2 + 1][1] = r[3];
                ldmat_x4(r, uBl + off);
                bl[ng * 2 + 0][0] = r[0]; bl[ng * 2 + 0][1] = r[2];
                bl[ng * 2 + 1][0] = r[1]; bl[ng * 2 + 1][1] = r[3];
            }
#pragma unroll
            for (int mt = 0; mt < 2; mt++)
#pragma unroll
                for (int nt = 0; nt < 4; nt++) {
                    mma_bf16(acc[mt][nt], ah[mt], bh[nt]);
                    mma_bf16(acc[mt][nt], ah[mt], bl[nt]);
                    mma_bf16(acc[mt][nt], al[mt], bh[nt]);
                }
        }
        __syncthreads();
    }

    // ---------------- Epilogue ----------------
    // acc coords: row = wm*32 + mt*16 + lane/4 (+8 for half=1), col = wn*32 + nt*8 + (lane%3)*2
    float se = 0.f, sq = 0.f;
    const int rbase = by * BM + wm * 32 + (lane >> 2);
    const int cbase = bx * BN + wn * 32 + (lane & 3) * 2;

    int kq[2][2];
    if (FUSED) {
#pragma unroll
        for (int mt = 0; mt < 2; mt++) {
            kq[mt][0] = Kidx[rbase + mt * 16];
            kq[mt][1] = Kidx[rbase + mt * 16 + 8];
        }
    }

#pragma unroll
    for (int mt = 0; mt < 2; mt++) {
#pragma unroll
        for (int half = 0; half < 2; half++) {
            const int r = rbase + mt * 16 + half * 8;
#pragma unroll
            for (int nt = 0; nt < 4; nt++) {
                const int cc = cbase + nt * 8;
                float v0 = acc[mt][nt][half * 2 + 0] + bias[cc];
                float v1 = acc[mt][nt][half * 2 + 1] + bias[cc + 1];
                if (!FUSED) {
                    if (ACT == 1) { v0 = fmaxf(v0, 0.f); v1 = fmaxf(v1, 0.f); }
                    else if (ACT == 2) { v0 = tanhf(v0); v1 = tanhf(v1); }
                    *(float2*)(C + (size_t)r * Ntot + cc) = make_float2(v0, v1);
                } else {
                    const float2 xv  = *(const float2*)(X  + (size_t)r * DIN + cc);
                    const float2 xqv = *(const float2*)(XQ + (size_t)kq[mt][half] * DIN + cc);
                    // Out = d_out + 1 is only 4B-aligned -> SCALAR stores (R6 fault fix)
                    float* op = Out + (size_t)r * DIN + cc;
                    op[0] = v0 + xqv.x;
                    op[1] = v1 + xqv.y;
                    float d;
                    d = xv.x - v0;    se = fmaf(d, d, se);
                    d = xv.y - v1;    se = fmaf(d, d, se);
                    d = xv.x - xqv.x; sq = fmaf(d, d, sq);
                    d = xv.y - xqv.y; sq = fmaf(d, d, sq);
                }
            }
        }
    }

    if (FUSED) {
        __syncthreads();                    // smem tiles dead; reuse for reduction
        float* r1 = (float*)smem;
        float* r2 = r1 + 256;
        r1[tid] = se; r2[tid] = sq;
        __syncthreads();
        for (int s = 128; s > 0; s >>= 1) {
            if (tid < s) { r1[tid] += r1[tid + s]; r2[tid] += r2[tid + s]; }
            __syncthreads();
        }
        if (tid == 0) {
            int bid = by * gridDim.x + bx;
            msee[bid] = r1[0];
            mseq[bid] = r2[0];
        }
    }
}

// ---------------------------------------------------------------------------
// Argmin + commit/som partials
// ---------------------------------------------------------------------------
__global__ __launch_bounds__(256) void argmin_som_kernel(
    const float* __restrict__ Z, const float* __restrict__ emb,
    int* __restrict__ Kout,
    float* __restrict__ commit_part, float* __restrict__ som_part)
{
    __shared__ float se_[NCODE * LAT];
    const int tid = threadIdx.x;
    for (int i = tid; i < NCODE * LAT; i += blockDim.x) se_[i] = emb[i];
    __syncthreads();

    const int b = blockIdx.x * blockDim.x + tid;
    float commit = 0.f, som = 0.f;
    if (b < NB) {
        const float* z = Z + (size_t)b * LAT;
        float zr[LAT];
        float zn = 0.f;
#pragma unroll
        for (int d = 0; d < LAT; d++) { zr[d] = z[d]; zn = fmaf(zr[d], zr[d], zn); }

        float dist[NCODE];
        int k = 0;
        float best = 3.4e38f;
#pragma unroll
        for (int c = 0; c < NCODE; c++) {
            float s = 0.f;
#pragma unroll
            for (int d = 0; d < LAT; d++) {
                float df = zr[d] - se_[c * LAT + d];
                s = fmaf(df, df, s);
            }
            dist[c] = s;
            if (s < best) { best = s; k = c; }
        }
        Kout[b] = k;
        const int k1 = k / 3, k2 = k % 3;
        commit = dist[k];
        som = dist[k];
        som += (k1 < 2) ? dist[(k1 + 1) * 3 + k2] : zn;
        som += (k1 > 0) ? dist[(k1 - 1) * 3 + k2] : zn;
        som += (k2 < 2) ? dist[k1 * 3 + k2 + 1]   : zn;
        som += (k2 > 0) ? dist[k1 * 3 + k2 - 1]   : zn;
    }

    __shared__ float r1[256], r2[256];
    r1[tid] = commit; r2[tid] = som;
    __syncthreads();
    for (int s = 128; s > 0; s >>= 1) {
        if (tid < s) { r1[tid] += r1[tid + s]; r2[tid] += r2[tid + s]; }
        __syncthreads();
    }
    if (tid == 0) { commit_part[blockIdx.x] = r1[0]; som_part[blockIdx.x] = r2[0]; }
}

// ---------------------------------------------------------------------------
// dec_q on the 9 codebook vectors
// ---------------------------------------------------------------------------
__global__ void dq_layer1(const float* __restrict__ emb, const float* __restrict__ w,
                          const float* __restrict__ bias, float* __restrict__ out)
{
    const int c = blockIdx.x, j = threadIdx.x;
    float s = bias[j];
    for (int d = 0; d < LAT; d++) s = fmaf(emb[c * LAT + d], w[d * HID + j], s);
    out[c * HID + j] = fmaxf(s, 0.f);
}
__global__ void dq_layer2(const float* __restrict__ h, const float* __restrict__ w,
                          const float* __restrict__ bias, float* __restrict__ out)
{
    const int c = blockIdx.x, j = threadIdx.x;
    float s = bias[j];
    for (int i = 0; i < HID; i++) s = fmaf(h[c * HID + i], w[i * HID + j], s);
    out[c * HID + j] = fmaxf(s, 0.f);
}
__global__ void dq_layer3(const float* __restrict__ h, const float* __restrict__ w,
                          const float* __restrict__ bias, float* __restrict__ out)
{
    const int c = blockIdx.y;
    const int n = blockIdx.x * blockDim.x + threadIdx.x;
    float s = bias[n];
    for (int i = 0; i < HID; i++) s = fmaf(h[c * HID + i], w[(size_t)i * DIN + n], s);
    out[c * DIN + n] = s;
}

// ---------------------------------------------------------------------------
// Finalize (4096 MSE partials)
// ---------------------------------------------------------------------------
__global__ void finalize_kernel(
    const float* __restrict__ mse_e, const float* __restrict__ mse_q,
    const float* __restrict__ commit, const float* __restrict__ som,
    float* __restrict__ out_loss, int has_loss)
{
    __shared__ double sh[256];
    const int tid = threadIdx.x;

    double a = 0.0;
    for (int i = tid; i < 4096; i += 256) a += (double)mse_e[i] + (double)mse_q[i];
    sh[tid] = a; __syncthreads();
    for (int s = 128; s > 0; s >>= 1) { if (tid < s) sh[tid] += sh[tid + s]; __syncthreads(); }
    const double mse_sum = sh[0]; __syncthreads();

    double c = 0.0;
    for (int i = tid; i < 64; i += 256) c += (double)commit[i];
    sh[tid] = c; __syncthreads();
    for (int s = 128; s > 0; s >>= 1) { if (tid < s) sh[tid] += sh[tid + s]; __syncthreads(); }
    const double commit_sum = sh[0]; __syncthreads();

    double so = 0.0;
    for (int i = tid; i < 64; i += 256) so += (double)som[i];
    sh[tid] = so; __syncthreads();
    for (int s = 128; s > 0; s >>= 1) { if (tid < s) sh[tid] += sh[tid + s]; __syncthreads(); }
    const double som_sum = sh[0];

    if (tid == 0 && has_loss) {
        const double loss = mse_sum    / ((double)NB * DIN)
                          + commit_sum / ((double)NB * LAT)
                          + som_sum    / ((double)NB * 5.0 * LAT);
        out_loss[0] = (float)loss;
    }
}

// ---------------------------------------------------------------------------
// Launch
// ---------------------------------------------------------------------------
extern "C" void kernel_launch(void* const* d_in, const int* in_sizes, int n_in,
                              void* d_out, int out_size)
{
    const float* x      = (const float*)d_in[0];
    const float* enc_w1 = (const float*)d_in[2];
    const float* enc_b1 = (const float*)d_in[3];
    const float* enc_w2 = (const float*)d_in[4];
    const float* enc_b2 = (const float*)d_in[5];
    const float* enc_w3 = (const float*)d_in[6];
    const float* enc_b3 = (const float*)d_in[7];
    const float* dq_w1  = (const float*)d_in[8];
    const float* dq_b1  = (const float*)d_in[9];
    const float* dq_w2  = (const float*)d_in[10];
    const float* dq_b2  = (const float*)d_in[11];
    const float* dq_w3  = (const float*)d_in[12];
    const float* dq_b3  = (const float*)d_in[13];
    const float* de_w1  = (const float*)d_in[14];
    const float* de_b1  = (const float*)d_in[15];
    const float* de_w2  = (const float*)d_in[16];
    const float* de_b2  = (const float*)d_in[17];
    const float* de_w3  = (const float*)d_in[18];
    const float* de_b3  = (const float*)d_in[19];
    const float* emb    = (const float*)d_in[20];

    float* out = (float*)d_out;
    long long arr_off = (long long)out_size - (long long)NB * DIN;
    if (arr_off < 0) arr_off = 0;
    float* outArr = out + arr_off;

    float *H1, *H2, *Z, *h1q, *h2q, *xq, *msee, *mseq, *comm, *som;
    int* Kp;
    __nv_bfloat16 *twh_e1, *twl_e1, *twh_e2, *twl_e2, *twh_e3, *twl_e3;
    __nv_bfloat16 *twh_d1, *twl_d1, *twh_d2, *twl_d2, *twh_d3, *twl_d3;
    cudaGetSymbolAddress((void**)&H1,  g_H1);
    cudaGetSymbolAddress((void**)&H2,  g_H2);
    cudaGetSymbolAddress((void**)&Z,   g_Z);
    cudaGetSymbolAddress((void**)&Kp,  g_K);
    cudaGetSymbolAddress((void**)&h1q, g_h1q);
    cudaGetSymbolAddress((void**)&h2q, g_h2q);
    cudaGetSymbolAddress((void**)&xq,  g_xq);
    cudaGetSymbolAddress((void**)&msee, g_mse_e_part);
    cudaGetSymbolAddress((void**)&mseq, g_mse_q_part);
    cudaGetSymbolAddress((void**)&comm, g_commit_part);
    cudaGetSymbolAddress((void**)&som,  g_som_part);
    cudaGetSymbolAddress((void**)&twh_e1, g_twh_e1); cudaGetSymbolAddress((void**)&twl_e1, g_twl_e1);
    cudaGetSymbolAddress((void**)&twh_e2, g_twh_e2); cudaGetSymbolAddress((void**)&twl_e2, g_twl_e2);
    cudaGetSymbolAddress((void**)&twh_e3, g_twh_e3); cudaGetSymbolAddress((void**)&twl_e3, g_twl_e3);
    cudaGetSymbolAddress((void**)&twh_d1, g_twh_d1); cudaGetSymbolAddress((void**)&twl_d1, g_twl_d1);
    cudaGetSymbolAddress((void**)&twh_d2, g_twh_d2); cudaGetSymbolAddress((void**)&twl_d2, g_twl_d2);
    cudaGetSymbolAddress((void**)&twh_d3, g_twh_d3); cudaGetSymbolAddress((void**)&twl_d3, g_twl_d3);

    // dynamic smem: (BM + BN) * PK * 2 arrays * 2 bytes = 192*72*4 = 55296
    const int SMEM = (BM + BN) * PK * 2 * 2;
    cudaFuncSetAttribute(gemm_mma<1, false>, cudaFuncAttributeMaxDynamicSharedMemorySize, SMEM);
    cudaFuncSetAttribute(gemm_mma<2, false>, cudaFuncAttributeMaxDynamicSharedMemorySize, SMEM);
    cudaFuncSetAttribute(gemm_mma<0, true >, cudaFuncAttributeMaxDynamicSharedMemorySize, SMEM);

    const dim3 blk(256);

    // Weight prep
    transpose_split<<<dim3(HID / 32, DIN / 32), blk>>>(enc_w1, DIN, HID, twh_e1, twl_e1);
    transpose_split<<<dim3(HID / 32, HID / 32), blk>>>(enc_w2, HID, HID, twh_e2, twl_e2);
    transpose_split<<<dim3(LAT / 32, HID / 32), blk>>>(enc_w3, HID, LAT, twh_e3, twl_e3);
    transpose_split<<<dim3(HID / 32, LAT / 32), blk>>>(de_w1,  LAT, HID, twh_d1, twl_d1);
    transpose_split<<<dim3(HID / 32, HID / 32), blk>>>(de_w2,  HID, HID, twh_d2, twl_d2);
    transpose_split<<<dim3(DIN / 32, HID / 32), blk>>>(de_w3,  HID, DIN, twh_d3, twl_d3);

    // Encoder
    gemm_mma<1, false><<<dim3(HID / BN, NB / BM), blk, SMEM>>>(x,  twh_e1, twl_e1, enc_b1, H1, DIN, HID,
                                                               nullptr, nullptr, nullptr, nullptr, nullptr, nullptr);
    gemm_mma<1, false><<<dim3(HID / BN, NB / BM), blk, SMEM>>>(H1, twh_e2, twl_e2, enc_b2, H2, HID, HID,
                                                               nullptr, nullptr, nullptr, nullptr, nullptr, nullptr);
    gemm_mma<2, false><<<dim3(LAT / BN, NB / BM), blk, SMEM>>>(H2, twh_e3, twl_e3, enc_b3, Z,  HID, LAT,
                                                               nullptr, nullptr, nullptr, nullptr, nullptr, nullptr);

    // Argmin + commit/som partials
    argmin_som_kernel<<<64, 256>>>(Z, emb, Kp, comm, som);

    // dec_q on the 9 codebook vectors
    dq_layer1<<<NCODE, HID>>>(emb, dq_w1, dq_b1, h1q);
    dq_layer2<<<NCODE, HID>>>(h1q, dq_w2, dq_b2, h2q);
    dq_layer3<<<dim3(8, NCODE), 256>>>(h2q, dq_w3, dq_b3, xq);

    // dec_e
    gemm_mma<1, false><<<dim3(HID / BN, NB / BM), blk, SMEM>>>(Z,  twh_d1, twl_d1, de_b1, H1, LAT, HID,
                                                               nullptr, nullptr, nullptr, nullptr, nullptr, nullptr);
    gemm_mma<1, false><<<dim3(HID / BN, NB / BM), blk, SMEM>>>(H1, twh_d2, twl_d2, de_b2, H2, HID, HID,
                                                               nullptr, nullptr, nullptr, nullptr, nullptr, nullptr);

    // Final fused GEMM + output + MSE partials: grid (32, 128) = 4096 partials
    gemm_mma<0, true><<<dim3(DIN / BN, NB / BM), blk, SMEM>>>(H2, twh_d3, twl_d3, de_b3, nullptr, HID, DIN,
                                                              x, xq, Kp, outArr, msee, mseq);

    // Loss
    finalize_kernel<<<1, 256>>>(msee, mseq, comm, som, out, (int)(arr_off > 0));
}